// round 12
// baseline (speedup 1.0000x reference)
#include <cuda_runtime.h>
#include <cuda_fp16.h>
#include <cstdint>

// ============================================================================
// Binarized-weight 3x3 conv, stride 1, pad 1, via implicit GEMM on HMMA
// (mma.sync m16n8k16 fp16 -> fp32 accum; arch-neutral PTX at compute_103).
// x: (32,128,64,64) f32 NCHW ; w: (256,128,3,3) f32 OIHW -> sign(w) ; out f32.
//
// Tile = 2 output rows x 64 cols (128 positions, zero waste) in padded 66x66
// space. Single-pass fp16 (~2e-4 rel_err). A halo loaded once per CTA;
// B double-buffered cp.async; B-fragments pipelined one k-slice ahead.
// R12: fix prep_x store width (uint2 -> uint4; R11 dropped half of x).
// ============================================================================

#define NPOS_STRIDE 4736ull   // 128 guard + 66*66 + tail guard
#define POS_BASE    128
#define N_TILES     32        // 32 output-row-pairs
#define A_ROWS      264       // rows [base-67, base+196] around the tile

// -------- scratch (zero-initialized device globals; guards stay 0) ----------
__device__ __half g_xh[32ull * NPOS_STRIDE * 128];
__device__ __half g_wb[2 * 9 * 256 * 64];   // [chunk*9+tap][co][ci64]

// ---------------------------- helpers ---------------------------------------
__device__ __forceinline__ uint32_t smem_u32(const void* p) {
    uint32_t a;
    asm("{ .reg .u64 t; cvta.to.shared.u64 t, %1; cvt.u32.u64 %0, t; }"
        : "=r"(a) : "l"(p));
    return a;
}

#define CP_ASYNC16(dst_u32, src_ptr) \
    asm volatile("cp.async.cg.shared.global [%0], [%1], 16;" \
                 :: "r"(dst_u32), "l"(src_ptr))
#define CP_COMMIT() asm volatile("cp.async.commit_group;" ::: "memory")
#define CP_WAIT0()  asm volatile("cp.async.wait_group 0;" ::: "memory")

__device__ __forceinline__ void ldsm_x4(uint32_t& r0, uint32_t& r1,
                                        uint32_t& r2, uint32_t& r3,
                                        uint32_t addr) {
    asm volatile("ldmatrix.sync.aligned.m8n8.x4.shared.b16 {%0,%1,%2,%3}, [%4];"
                 : "=r"(r0), "=r"(r1), "=r"(r2), "=r"(r3) : "r"(addr));
}

__device__ __forceinline__ void mma_f16(float* c, const uint32_t* a,
                                        uint32_t b0, uint32_t b1) {
    asm volatile(
        "mma.sync.aligned.m16n8k16.row.col.f32.f16.f16.f32 "
        "{%0,%1,%2,%3}, {%4,%5,%6,%7}, {%8,%9}, {%0,%1,%2,%3};"
        : "+f"(c[0]), "+f"(c[1]), "+f"(c[2]), "+f"(c[3])
        : "r"(a[0]), "r"(a[1]), "r"(a[2]), "r"(a[3]), "r"(b0), "r"(b1));
}

// ----------------- merged pre-kernel: pad/transpose x + weights --------------
// blocks [0, 2048): x prep (h = b & 63, n = b >> 6), vectorized 16B stores
// blocks [2048, 2304): w prep, one block per co, coalesced plane writes
__global__ void __launch_bounds__(256) prep_all(const float* __restrict__ x,
                                                const float* __restrict__ w) {
    const int b = blockIdx.x;
    const int t = threadIdx.x;
    if (b < 2048) {
        __shared__ float st[64 * 129];
        const int h = b & 63, n = b >> 6;
        for (int idx = t; idx < 8192; idx += 256) {
            int ci = idx >> 6, ww = idx & 63;
            st[ww * 129 + ci] = x[(((size_t)n * 128 + ci) * 64 + h) * 64 + ww];
        }
        __syncthreads();
        // 8 halves (16B) per store: idx2 -> (w = idx2>>4, ci8 = idx2&15)
        const size_t rowbase = (size_t)n * NPOS_STRIDE + POS_BASE +
                               (size_t)(h + 1) * 66 + 1;
        for (int idx2 = t; idx2 < 1024; idx2 += 256) {
            const int ww = idx2 >> 4, ci0 = (idx2 & 15) << 3;
            const float* src = &st[ww * 129 + ci0];
            __half2 hv[4];
#pragma unroll
            for (int k = 0; k < 4; k++)
                hv[k] = __floats2half2_rn(src[2 * k], src[2 * k + 1]);
            *(uint4*)(g_xh + (rowbase + ww) * 128 + ci0) = *(uint4*)hv;
        }
    } else {
        const int co = b - 2048;
        __shared__ __half ss[1152];        // [ci][tap]
        for (int i = t; i < 1152; i += 256) {
            float v = w[co * 1152 + i];
            ss[i] = __float2half_rn((v > 0.f) ? 1.f : ((v < 0.f) ? -1.f : 0.f));
        }
        __syncthreads();
        // planes: (chunk*9+tap); write 64 contiguous halves per plane
        for (int i2 = t; i2 < 1152; i2 += 256) {
            const int plane = i2 >> 6, ci = i2 & 63;
            const int chunk = plane / 9, tap = plane - chunk * 9;
            g_wb[(plane << 14) + (co << 6) + ci] =
                ss[((chunk << 6) + ci) * 9 + tap];
        }
    }
}

// ------------------------------- main kernel ---------------------------------
// dynamic smem layout (bytes):
//   A  : [0,     67584)   264 rows x 256B (128 ci), swizzled; loaded ONCE
//   B0 : [67584, 83968)   128 rows x 128B (64 ci), swizzled (double-buffered)
//   B1 : [83968, 100352)
//   D (epilogue, reuses A): 128co x 132 floats = 67584B
#define SM_A     0
#define SM_B0    67584
#define SM_B1    83968
#define SM_TOTAL 100352

__global__ void __launch_bounds__(256, 2)
bconv_hmma(float* __restrict__ out) {
    extern __shared__ char sm[];
    const uint32_t smb = smem_u32(sm);

    const int t    = threadIdx.x;
    const int wid  = t >> 5;
    const int lane = t & 31;
    const int n    = blockIdx.z;
    const int coB  = blockIdx.y;           // 0/1 -> co block of 128
    const int tile = blockIdx.x;           // output rows (2*tile, 2*tile+1)

    const int mw = wid & 1;                // 2 m-halves of 64 positions
    const int nw = wid >> 1;               // 4 n-quarters of 32 co

    // lane-invariant ldmatrix offsets
    const int q  = lane >> 3;
    const int rA = (lane & 7) + ((q & 1) << 3);     // A row-in-tile
    const int cA = q >> 1;                          // A k-half (16B unit)
    const int rB = (lane & 7) + ((lane >> 4) << 3); // B row-in-pair
    const int cB = q & 1;                           // B k-half

    // B addressing constants (invariant across iters, mod the buffer base)
    const uint32_t bRowOff = (uint32_t)(nw * 32 + rB) * 128;
    const uint32_t bXorM   = (uint32_t)(rB & 7);    // (nw*32+rB)&7 == rB&7

    float acc[4][4][4];
#pragma unroll
    for (int i = 0; i < 4; i++)
#pragma unroll
        for (int j = 0; j < 4; j++)
#pragma unroll
            for (int k = 0; k < 4; k++) acc[i][j][k] = 0.f;

    // halo row 0 = padded position 132*tile (tile base = 132*tile + 67)
    const size_t xrow0 = ((size_t)n * NPOS_STRIDE + POS_BASE + 132 * tile) * 128;
    const __half* wbase = g_wb + (coB << 13);   // co block offset

    // ---- prologue: prefetch B(iter 0), then full A halo (once) ----
    for (int i = t; i < 1024; i += 256) {
        const int r = i >> 3, j = i & 7;
        const uint32_t doff = (uint32_t)(r * 128 + ((j ^ (r & 7)) << 4));
        CP_ASYNC16(smb + SM_B0 + doff, wbase + (i << 3));
    }
    CP_COMMIT();
    for (int i = t; i < A_ROWS * 16; i += 256) {
        const int r = i >> 4, j = i & 15;
        const size_t gsrc = xrow0 + (size_t)r * 128 + (j << 3);
        const uint32_t doff = (uint32_t)(r * 256 + ((j ^ (r & 7)) << 4));
        CP_ASYNC16(smb + SM_A + doff, g_xh + gsrc);
    }
    CP_COMMIT();

#pragma unroll 1
    for (int iter = 0; iter < 18; ++iter) {
        const int chunk = iter / 9;
        const int tap   = iter - chunk * 9;

        CP_WAIT0();            // B(iter) landed (iter 0: + A halo)
        __syncthreads();       // frees the other B buffer for prefetch

        if (iter < 17) {       // ---- prefetch next iter's B ----
            const __half* src = wbase + ((iter + 1) << 14);
            const uint32_t bdst = smb + (((iter + 1) & 1) ? SM_B1 : SM_B0);
            for (int i = t; i < 1024; i += 256) {
                const int r = i >> 3, j = i & 7;
                const uint32_t doff = (uint32_t)(r * 128 + ((j ^ (r & 7)) << 4));
                CP_ASYNC16(bdst + doff, src + (i << 3));
            }
            CP_COMMIT();
        }

        // ---- compute tap/chunk ----
        const int s = (tap / 3 - 1) * 66 + (tap % 3 - 1);
        const int aRow0 = mw * 66 + s + 67 + rA;     // 16-row steps keep &7
        const uint32_t aBase = smb + SM_A + (uint32_t)aRow0 * 256;
        const uint32_t aXorM = (uint32_t)(aRow0 & 7);
        const uint32_t bBase = smb + ((iter & 1) ? SM_B1 : SM_B0) + bRowOff;
        const int cbase = chunk << 3;                // A column base, 16B units

        uint32_t bf[2][4][2];
        // preload B frags for ks=0
#pragma unroll
        for (int pr = 0; pr < 2; pr++) {
            const uint32_t addr = bBase + pr * 2048 + (((uint32_t)cB ^ bXorM) << 4);
            ldsm_x4(bf[0][pr * 2][0], bf[0][pr * 2][1],
                    bf[0][pr * 2 + 1][0], bf[0][pr * 2 + 1][1], addr);
        }

#pragma unroll
        for (int ks = 0; ks < 4; ks++) {
            const int cur = ks & 1;
            uint32_t af[4][4];
#pragma unroll
            for (int mt = 0; mt < 4; mt++) {
                const uint32_t addr = aBase + mt * 4096 +
                    (((uint32_t)(cbase + 2 * ks + cA) ^ aXorM) << 4);
                ldsm_x4(af[mt][0], af[mt][1], af[mt][2], af[mt][3], addr);
            }
            if (ks < 3) {      // prefetch next ks' B frags into the other slot
#pragma unroll
                for (int pr = 0; pr < 2; pr++) {
                    const uint32_t addr = bBase + pr * 2048 +
                        (((uint32_t)(2 * (ks + 1) + cB) ^ bXorM) << 4);
                    ldsm_x4(bf[cur ^ 1][pr * 2][0], bf[cur ^ 1][pr * 2][1],
                            bf[cur ^ 1][pr * 2 + 1][0], bf[cur ^ 1][pr * 2 + 1][1],
                            addr);
                }
            }
#pragma unroll
            for (int mt = 0; mt < 4; mt++)
#pragma unroll
                for (int nt = 0; nt < 4; nt++)
                    mma_f16(acc[mt][nt], af[mt], bf[cur][nt][0], bf[cur][nt][1]);
        }
    }

    // ---- epilogue: acc -> smem D [co][132] -> coalesced gmem (no masking) ----
    __syncthreads();
    float* D = (float*)sm;
    const int gRow = lane >> 2;
    const int gCol = (lane & 3) * 2;
#pragma unroll
    for (int mt = 0; mt < 4; mt++) {
#pragma unroll
        for (int nt = 0; nt < 4; nt++) {
            const int pl  = mw * 64 + mt * 16 + gRow;
            const int col = nw * 32 + nt * 8 + gCol;
            D[col * 132 + pl]           = acc[mt][nt][0];
            D[(col + 1) * 132 + pl]     = acc[mt][nt][1];
            D[col * 132 + pl + 8]       = acc[mt][nt][2];
            D[(col + 1) * 132 + pl + 8] = acc[mt][nt][3];
        }
    }
    __syncthreads();

    // p_l: 0..63 -> output row 2*tile, 64..127 -> 2*tile+1; col = p_l & 63
    for (int i = t; i < 128 * 128; i += 256) {
        const int co_l = i >> 7, p_l = i & 127;
        const int h = 2 * tile + (p_l >> 6);
        out[(((size_t)n * 256 + coB * 128 + co_l) << 12) + (h << 6) + (p_l & 63)]
            = D[co_l * 132 + p_l];
    }
}

// ------------------------------- launcher ------------------------------------
extern "C" void kernel_launch(void* const* d_in, const int* in_sizes, int n_in,
                              void* d_out, int out_size) {
    const float* x = (const float*)d_in[0];
    const float* w = (const float*)d_in[1];
    float* out = (float*)d_out;

    cudaFuncSetAttribute(bconv_hmma, cudaFuncAttributeMaxDynamicSharedMemorySize,
                         SM_TOTAL);

    prep_all<<<2304, 256>>>(x, w);
    bconv_hmma<<<dim3(N_TILES, 2, 32), 256, SM_TOTAL>>>(out);
}